// round 2
// baseline (speedup 1.0000x reference)
#include <cuda_runtime.h>

// PCEN: M = EMA(data, s=0.5) along T;  out = (x/(eps+M)^alpha + delta)^r - delta^r
// data: [F=1024, T=50000] fp32 row-major. alpha/r/delta: 1-elem fp32 arrays.
//
// Key trick: EMA decay is 0.5, so state K steps back contributes 0.5^K.
// With K=32 the truncation error is 2.3e-10 — we re-initialize the scan at
// every tile from a 32-sample halo, making all tiles independent.

#define F_DIM   1024
#define BLOCK   256
#define CPT     32                 // elements per thread (serial recurrence run)
#define TILE    (BLOCK * CPT)      // 8192
#define HALO    32                 // lookback window; 0.5^32 tail dropped
#define SIDX(j) ((j) + ((j) >> 5)) // smem bank-skew: kills 32-way conflicts

__global__ __launch_bounds__(BLOCK)
void pcen_kernel(const float* __restrict__ data,
                 const float* __restrict__ alpha_p,
                 const float* __restrict__ r_p,
                 const float* __restrict__ delta_p,
                 float* __restrict__ out,
                 int T)
{
    __shared__ float sm[SIDX(TILE + HALO) + 1];

    const int row    = blockIdx.y;
    const int tile0  = blockIdx.x * TILE;            // first t of this tile
    const long long rowBase = (long long)row * T;
    const int tid    = threadIdx.x;

    // ---- Phase 1: coalesced load of tile + left halo into smem ----
    // smem index j corresponds to global t = tile0 - HALO + j
    #pragma unroll 4
    for (int j = tid; j < TILE + HALO; j += BLOCK) {
        const int t = tile0 - HALO + j;
        float v = 0.0f;                               // t<0 -> zero (matches zero init state)
        if (t >= 0 && t < T) v = data[rowBase + t];
        sm[SIDX(j)] = v;
    }

    const float alpha = *alpha_p;
    const float r     = *r_p;
    const float delta = *delta_p;
    const float dr    = exp2f(r * __log2f(delta));   // delta^r, once per thread

    __syncthreads();

    // ---- Phase 2: init EMA state just before this thread's chunk ----
    // M_{t0-1} = sum_{j=1..HALO} 0.5^j * x[t0-j]   (truncated, error <= 0.5^32)
    const int start = tid * CPT;                      // chunk start within tile
    float M = 0.0f;
    float w = 0.5f;
    #pragma unroll
    for (int j = 1; j <= HALO; ++j) {
        M = fmaf(w, sm[SIDX(HALO + start - j)], M);
        w *= 0.5f;
    }

    __syncthreads();  // all inits read old halo data before in-place overwrite

    // ---- Phase 3: exact serial recurrence over the chunk + PCEN math ----
    #pragma unroll 8
    for (int c = 0; c < CPT; ++c) {
        const int j = HALO + start + c;
        const float x = sm[SIDX(j)];
        M = 0.5f * (M + x);                           // M_t = 0.5*M_{t-1} + 0.5*x_t
        const float m   = 1e-6f + M;
        const float inv = exp2f(-alpha * __log2f(m));     // (eps+M)^(-alpha)
        const float y   = fmaf(x, inv, delta);
        sm[SIDX(j)] = exp2f(r * __log2f(y)) - dr;         // y^r - delta^r
    }

    __syncthreads();

    // ---- Phase 4: coalesced store ----
    #pragma unroll 4
    for (int j = tid; j < TILE; j += BLOCK) {
        const int t = tile0 + j;
        if (t < T) out[rowBase + t] = sm[SIDX(HALO + j)];
    }
}

extern "C" void kernel_launch(void* const* d_in, const int* in_sizes, int n_in,
                              void* d_out, int out_size)
{
    const float* data    = (const float*)d_in[0];
    const float* alpha_p = (const float*)d_in[1];
    const float* r_p     = (const float*)d_in[2];
    const float* delta_p = (const float*)d_in[3];
    float* out = (float*)d_out;

    const int total = in_sizes[0];
    const int T = total / F_DIM;
    const int tilesPerRow = (T + TILE - 1) / TILE;

    dim3 grid(tilesPerRow, F_DIM);
    pcen_kernel<<<grid, BLOCK>>>(data, alpha_p, r_p, delta_p, out, T);
}

// round 4
// speedup vs baseline: 1.3776x; 1.3776x over previous
#include <cuda_runtime.h>

// PCEN: M = EMA(data, s=0.5) along T;  out = (x/(eps+M)^alpha + delta)^r - delta^r
// data: [F=1024, T=50000] fp32 row-major. alpha/r/delta: 1-elem fp32 arrays.
//
// EMA decay 0.5 => 32-sample halo re-init (truncation 0.5^32 ~ 2.3e-10).
// Full 128-bit vectorization. Smem layout: 32-float groups padded to 36
// floats (9 float4s). Odd float4 stride => conflict-free LDS.128/STS.128.
// R4 fix: halo-init weight ladder starts at 2^-33 (was 2^-32, doubling every
// weight: e=0 must get 0.5^32, e=31 must get 0.5^1).

#define F_DIM   1024
#define BLOCK   256
#define CPT     32                    // floats per thread chunk (= 1 group)
#define TILE    (BLOCK * CPT)         // 8192 floats
#define HALO    32                    // 1 group
#define NV4     ((TILE + HALO) / 4)   // 2056 float4 incl halo
#define TV4     (TILE / 4)            // 2048 float4 of payload
#define SM4(j4) ((j4) + ((j4) >> 3))  // logical float4 idx -> padded smem idx
#define NGROUPS ((TILE + HALO) / 32)  // 257
#define SMSZ4   (NGROUPS * 9)         // 2313 float4 = 37008 B

__device__ __forceinline__ float pcen_elem(float x, float& M,
                                           float alpha, float r,
                                           float delta, float dr)
{
    M = 0.5f * M + 0.5f * x;                       // M_t = 0.5*(M_{t-1}+x_t)
    const float m   = M + 1e-6f;
    const float inv = exp2f(-alpha * __log2f(m));  // (eps+M)^(-alpha)
    const float y   = fmaf(x, inv, delta);
    return exp2f(r * __log2f(y)) - dr;             // y^r - delta^r
}

__global__ __launch_bounds__(BLOCK)
void pcen_kernel(const float4* __restrict__ data4,
                 const float*  __restrict__ alpha_p,
                 const float*  __restrict__ r_p,
                 const float*  __restrict__ delta_p,
                 float4* __restrict__ out4,
                 int T4)                            // T/4 (=12500)
{
    __shared__ float4 sm4[SMSZ4];

    const int tid     = threadIdx.x;
    const int tile0_4 = blockIdx.x * TV4;           // tile start (float4 units)
    const long long rowBase4 = (long long)blockIdx.y * T4;
    const int haloBase4 = tile0_4 - HALO / 4;       // global float4 idx of smem j4=0

    const bool interior = (haloBase4 >= 0) && (tile0_4 + TV4 <= T4);

    // ---- Phase 1: coalesced LDG.128 of tile + left halo -> smem ----
    if (interior) {
        #pragma unroll
        for (int k = 0; k < 8; ++k) {
            const int j4 = tid + k * BLOCK;
            sm4[SM4(j4)] = data4[rowBase4 + haloBase4 + j4];
        }
        // remainder: NV4 - 8*BLOCK = 8 float4s
        if (tid < NV4 - 8 * BLOCK) {
            const int j4 = tid + 8 * BLOCK;
            sm4[SM4(j4)] = data4[rowBase4 + haloBase4 + j4];
        }
    } else {
        for (int j4 = tid; j4 < NV4; j4 += BLOCK) {
            const int t4 = haloBase4 + j4;
            float4 v = make_float4(0.f, 0.f, 0.f, 0.f);
            if (t4 >= 0 && t4 < T4) v = data4[rowBase4 + t4];
            sm4[SM4(j4)] = v;
        }
    }

    const float alpha = *alpha_p;
    const float r     = *r_p;
    const float delta = *delta_p;
    const float dr    = exp2f(r * __log2f(delta));

    __syncthreads();

    // ---- Phase 2: init EMA state from the 32 samples before this chunk ----
    // Thread tid's chunk = group tid+1; preceding 32 floats = group tid.
    // M_init = sum_e x_e * 0.5^(32-e)  (e = 0..31 within group tid)
    float M = 0.0f;
    {
        const int g4 = 9 * tid;                    // smem float4 idx of group tid
        float w = 0x1p-33f;                        // doubles BEFORE each fma -> e=0 gets 2^-32
        #pragma unroll
        for (int k = 0; k < 8; ++k) {
            const float4 v = sm4[g4 + k];
            w *= 2.0f; M = fmaf(v.x, w, M);
            w *= 2.0f; M = fmaf(v.y, w, M);
            w *= 2.0f; M = fmaf(v.z, w, M);
            w *= 2.0f; M = fmaf(v.w, w, M);
        }
    }

    __syncthreads();   // all halo reads done before in-place overwrite

    // ---- Phase 3: exact serial recurrence over chunk + PCEN, in place ----
    {
        const int b4 = 9 * (tid + 1);              // smem float4 idx of own chunk
        #pragma unroll
        for (int k = 0; k < 8; ++k) {
            const float4 xv = sm4[b4 + k];
            float4 res;
            res.x = pcen_elem(xv.x, M, alpha, r, delta, dr);
            res.y = pcen_elem(xv.y, M, alpha, r, delta, dr);
            res.z = pcen_elem(xv.z, M, alpha, r, delta, dr);
            res.w = pcen_elem(xv.w, M, alpha, r, delta, dr);
            sm4[b4 + k] = res;
        }
    }

    __syncthreads();

    // ---- Phase 4: coalesced STG.128 of results ----
    if (interior) {
        #pragma unroll
        for (int k = 0; k < 8; ++k) {
            const int j4 = tid + k * BLOCK;        // payload float4 idx
            out4[rowBase4 + tile0_4 + j4] = sm4[SM4(j4 + HALO / 4)];
        }
    } else {
        #pragma unroll
        for (int k = 0; k < 8; ++k) {
            const int j4 = tid + k * BLOCK;
            const int t4 = tile0_4 + j4;
            if (t4 < T4) out4[rowBase4 + t4] = sm4[SM4(j4 + HALO / 4)];
        }
    }
}

extern "C" void kernel_launch(void* const* d_in, const int* in_sizes, int n_in,
                              void* d_out, int out_size)
{
    const float4* data4   = (const float4*)d_in[0];
    const float*  alpha_p = (const float*)d_in[1];
    const float*  r_p     = (const float*)d_in[2];
    const float*  delta_p = (const float*)d_in[3];
    float4* out4 = (float4*)d_out;

    const int total = in_sizes[0];
    const int T  = total / F_DIM;                   // 50000
    const int T4 = T / 4;                           // 12500 (T % 4 == 0)
    const int tilesPerRow = (T + TILE - 1) / TILE;  // 7

    dim3 grid(tilesPerRow, F_DIM);
    pcen_kernel<<<grid, BLOCK>>>(data4, alpha_p, r_p, delta_p, out4, T4);
}

// round 5
// speedup vs baseline: 1.5678x; 1.1381x over previous
#include <cuda_runtime.h>

// PCEN: M = EMA(data, s=0.5) along T;  out = (x/(eps+M)^alpha + delta)^r - delta^r
// data: [F=1024, T=50000] fp32 row-major. alpha/r/delta: 1-elem fp32 arrays.
//
// EMA decay 0.5 => 16-sample halo re-init (truncation 0.5^16 ~ 1.5e-5, gate 1e-3).
// R5: CPT=16 / 20.6KB smem -> 8 blocks/SM (100% occ); r==0.5 sqrt fast path
// (4 MUFU -> 3 per element); int32 indexing.
// Smem: 16-float groups padded to 20 floats (5 float4). Odd float4 stride =>
// conflict-free LDS.128/STS.128 for per-thread chunk access.

#define F_DIM   1024
#define BLOCK   256
#define CPT     16                    // floats per thread chunk (= 1 group)
#define TILE    (BLOCK * CPT)         // 4096 floats
#define HALO    16                    // 1 group lookback
#define NV4     ((TILE + HALO) / 4)   // 1028 float4 incl halo
#define TV4     (TILE / 4)            // 1024 float4 payload
#define SM4(j4) ((j4) + ((j4) >> 2))  // logical float4 idx -> padded (4 -> 5 per group)
#define NGROUPS (TILE / 16 + 1)       // 257
#define SMSZ4   (NGROUPS * 5)         // 1285 float4 = 20560 B

// generic-r element
__device__ __forceinline__ float pcen_g(float x, float& M, float alpha,
                                        float r, float delta, float dr)
{
    M = 0.5f * (M + x);
    const float inv = exp2f(-alpha * __log2f(M + 1e-6f));
    const float y   = fmaf(x, inv, delta);
    return exp2f(r * __log2f(y)) - dr;
}

// r == 0.5 element: y^0.5 = sqrtf(y)  (1 MUFU instead of LG2+EX2)
__device__ __forceinline__ float pcen_h(float x, float& M, float alpha,
                                        float delta, float dr)
{
    M = 0.5f * (M + x);
    const float inv = exp2f(-alpha * __log2f(M + 1e-6f));
    const float y   = fmaf(x, inv, delta);
    return sqrtf(y) - dr;
}

__global__ __launch_bounds__(BLOCK)
void pcen_kernel(const float4* __restrict__ data4,
                 const float*  __restrict__ alpha_p,
                 const float*  __restrict__ r_p,
                 const float*  __restrict__ delta_p,
                 float4* __restrict__ out4,
                 int T4)                            // T/4 (=12500)
{
    __shared__ float4 sm4[SMSZ4];

    const int tid      = threadIdx.x;
    const int tile0_4  = blockIdx.x * TV4;
    const int rowBase4 = blockIdx.y * T4;           // < 12.8M, int ok
    const int haloBase4 = tile0_4 - HALO / 4;

    const bool interior = (haloBase4 >= 0) && (tile0_4 + TV4 <= T4);

    // ---- Phase 1: coalesced LDG.128 of tile + left halo -> smem ----
    if (interior) {
        #pragma unroll
        for (int k = 0; k < 4; ++k) {
            const int j4 = tid + k * BLOCK;
            sm4[SM4(j4)] = data4[rowBase4 + haloBase4 + j4];
        }
        if (tid < NV4 - 4 * BLOCK) {                // 4 leftover float4
            const int j4 = tid + 4 * BLOCK;
            sm4[SM4(j4)] = data4[rowBase4 + haloBase4 + j4];
        }
    } else {
        for (int j4 = tid; j4 < NV4; j4 += BLOCK) {
            const int t4 = haloBase4 + j4;
            float4 v = make_float4(0.f, 0.f, 0.f, 0.f);
            if (t4 >= 0 && t4 < T4) v = data4[rowBase4 + t4];
            sm4[SM4(j4)] = v;
        }
    }

    const float alpha = *alpha_p;
    const float r     = *r_p;
    const float delta = *delta_p;
    const bool  rhalf = (r == 0.5f);
    const float dr    = rhalf ? sqrtf(delta) : exp2f(r * __log2f(delta));

    __syncthreads();

    // ---- Phase 2: init EMA state from the 16 samples before the chunk ----
    // M_init = sum_{e=0..15} x_e * 0.5^(16-e)  (group tid; chunk = group tid+1)
    float M = 0.0f;
    {
        const int g4 = 5 * tid;
        float w = 0x1p-17f;                          // doubles before each fma
        #pragma unroll
        for (int k = 0; k < 4; ++k) {
            const float4 v = sm4[g4 + k];
            w *= 2.0f; M = fmaf(v.x, w, M);
            w *= 2.0f; M = fmaf(v.y, w, M);
            w *= 2.0f; M = fmaf(v.z, w, M);
            w *= 2.0f; M = fmaf(v.w, w, M);
        }
    }

    __syncthreads();   // halo reads done before in-place overwrite

    // ---- Phase 3: exact serial recurrence + PCEN, in place ----
    {
        const int b4 = 5 * (tid + 1);
        if (rhalf) {
            #pragma unroll
            for (int k = 0; k < 4; ++k) {
                const float4 xv = sm4[b4 + k];
                float4 res;
                res.x = pcen_h(xv.x, M, alpha, delta, dr);
                res.y = pcen_h(xv.y, M, alpha, delta, dr);
                res.z = pcen_h(xv.z, M, alpha, delta, dr);
                res.w = pcen_h(xv.w, M, alpha, delta, dr);
                sm4[b4 + k] = res;
            }
        } else {
            #pragma unroll
            for (int k = 0; k < 4; ++k) {
                const float4 xv = sm4[b4 + k];
                float4 res;
                res.x = pcen_g(xv.x, M, alpha, r, delta, dr);
                res.y = pcen_g(xv.y, M, alpha, r, delta, dr);
                res.z = pcen_g(xv.z, M, alpha, r, delta, dr);
                res.w = pcen_g(xv.w, M, alpha, r, delta, dr);
                sm4[b4 + k] = res;
            }
        }
    }

    __syncthreads();

    // ---- Phase 4: coalesced STG.128 ----
    if (interior) {
        #pragma unroll
        for (int k = 0; k < 4; ++k) {
            const int j4 = tid + k * BLOCK;
            out4[rowBase4 + tile0_4 + j4] = sm4[SM4(j4 + HALO / 4)];
        }
    } else {
        #pragma unroll
        for (int k = 0; k < 4; ++k) {
            const int j4 = tid + k * BLOCK;
            const int t4 = tile0_4 + j4;
            if (t4 < T4) out4[rowBase4 + t4] = sm4[SM4(j4 + HALO / 4)];
        }
    }
}

extern "C" void kernel_launch(void* const* d_in, const int* in_sizes, int n_in,
                              void* d_out, int out_size)
{
    const float4* data4   = (const float4*)d_in[0];
    const float*  alpha_p = (const float*)d_in[1];
    const float*  r_p     = (const float*)d_in[2];
    const float*  delta_p = (const float*)d_in[3];
    float4* out4 = (float4*)d_out;

    const int total = in_sizes[0];
    const int T  = total / F_DIM;                   // 50000
    const int T4 = T / 4;                           // 12500
    const int tilesPerRow = (T + TILE - 1) / TILE;  // 13

    dim3 grid(tilesPerRow, F_DIM);
    pcen_kernel<<<grid, BLOCK>>>(data4, alpha_p, r_p, delta_p, out4, T4);
}

// round 6
// speedup vs baseline: 1.6664x; 1.0629x over previous
#include <cuda_runtime.h>

// PCEN: M = EMA(data, s=0.5) along T;  out = (x/(eps+M)^alpha + delta)^r - delta^r
// data: [F=1024, T=50000] fp32 row-major. alpha/r/delta: 1-elem fp32 arrays.
//
// EMA decay 0.5 => 16-sample halo re-init (truncation 0.5^16 ~ 1.5e-5, gate 1e-3).
// CPT=16 / 20.6KB smem -> 8 blocks/SM; r==0.5 sqrt fast path; int32 indexing.
// Smem: 16-float groups padded to 20 floats (5 float4), conflict-free LDS.128.
// R6: raw-MUFU math via inline PTX (ex2/lg2/sqrt .approx) — replaces libm
// exp2f/sqrtf fixup sequences (~17 -> ~8 instrs/element of math).

#define F_DIM   1024
#define BLOCK   256
#define CPT     16                    // floats per thread chunk (= 1 group)
#define TILE    (BLOCK * CPT)         // 4096 floats
#define HALO    16                    // 1 group lookback
#define NV4     ((TILE + HALO) / 4)   // 1028 float4 incl halo
#define TV4     (TILE / 4)            // 1024 float4 payload
#define SM4(j4) ((j4) + ((j4) >> 2))  // logical float4 idx -> padded (4 -> 5 per group)
#define NGROUPS (TILE / 16 + 1)       // 257
#define SMSZ4   (NGROUPS * 5)         // 1285 float4 = 20560 B

__device__ __forceinline__ float ex2a(float x)  { float y; asm("ex2.approx.f32 %0, %1;"  : "=f"(y) : "f"(x)); return y; }
__device__ __forceinline__ float lg2a(float x)  { float y; asm("lg2.approx.f32 %0, %1;"  : "=f"(y) : "f"(x)); return y; }
__device__ __forceinline__ float sqrta(float x) { float y; asm("sqrt.approx.f32 %0, %1;" : "=f"(y) : "f"(x)); return y; }

// generic-r element: 4 MUFU
__device__ __forceinline__ float pcen_g(float x, float& M, float alpha,
                                        float r, float delta, float dr)
{
    M = 0.5f * (M + x);
    const float inv = ex2a(-alpha * lg2a(M + 1e-6f));
    const float y   = fmaf(x, inv, delta);
    return ex2a(r * lg2a(y)) - dr;
}

// r == 0.5 element: 3 MUFU
__device__ __forceinline__ float pcen_h(float x, float& M, float alpha,
                                        float delta, float dr)
{
    M = 0.5f * (M + x);
    const float inv = ex2a(-alpha * lg2a(M + 1e-6f));
    const float y   = fmaf(x, inv, delta);
    return sqrta(y) - dr;
}

__global__ __launch_bounds__(BLOCK)
void pcen_kernel(const float4* __restrict__ data4,
                 const float*  __restrict__ alpha_p,
                 const float*  __restrict__ r_p,
                 const float*  __restrict__ delta_p,
                 float4* __restrict__ out4,
                 int T4)                            // T/4 (=12500)
{
    __shared__ float4 sm4[SMSZ4];

    const int tid      = threadIdx.x;
    const int tile0_4  = blockIdx.x * TV4;
    const int rowBase4 = blockIdx.y * T4;           // < 12.8M, int ok
    const int haloBase4 = tile0_4 - HALO / 4;

    const bool interior = (haloBase4 >= 0) && (tile0_4 + TV4 <= T4);

    // ---- Phase 1: coalesced LDG.128 of tile + left halo -> smem ----
    if (interior) {
        #pragma unroll
        for (int k = 0; k < 4; ++k) {
            const int j4 = tid + k * BLOCK;
            sm4[SM4(j4)] = data4[rowBase4 + haloBase4 + j4];
        }
        if (tid < NV4 - 4 * BLOCK) {                // 4 leftover float4
            const int j4 = tid + 4 * BLOCK;
            sm4[SM4(j4)] = data4[rowBase4 + haloBase4 + j4];
        }
    } else {
        for (int j4 = tid; j4 < NV4; j4 += BLOCK) {
            const int t4 = haloBase4 + j4;
            float4 v = make_float4(0.f, 0.f, 0.f, 0.f);
            if (t4 >= 0 && t4 < T4) v = data4[rowBase4 + t4];
            sm4[SM4(j4)] = v;
        }
    }

    const float alpha = *alpha_p;
    const float r     = *r_p;
    const float delta = *delta_p;
    const bool  rhalf = (r == 0.5f);
    const float dr    = rhalf ? sqrta(delta) : ex2a(r * lg2a(delta));

    __syncthreads();

    // ---- Phase 2: init EMA state from the 16 samples before the chunk ----
    // M_init = sum_{e=0..15} x_e * 0.5^(16-e)  (group tid; chunk = group tid+1)
    float M = 0.0f;
    {
        const int g4 = 5 * tid;
        float w = 0x1p-17f;                          // doubles before each fma
        #pragma unroll
        for (int k = 0; k < 4; ++k) {
            const float4 v = sm4[g4 + k];
            w *= 2.0f; M = fmaf(v.x, w, M);
            w *= 2.0f; M = fmaf(v.y, w, M);
            w *= 2.0f; M = fmaf(v.z, w, M);
            w *= 2.0f; M = fmaf(v.w, w, M);
        }
    }

    __syncthreads();   // halo reads done before in-place overwrite

    // ---- Phase 3: exact serial recurrence + PCEN, in place ----
    {
        const int b4 = 5 * (tid + 1);
        if (rhalf) {
            #pragma unroll
            for (int k = 0; k < 4; ++k) {
                const float4 xv = sm4[b4 + k];
                float4 res;
                res.x = pcen_h(xv.x, M, alpha, delta, dr);
                res.y = pcen_h(xv.y, M, alpha, delta, dr);
                res.z = pcen_h(xv.z, M, alpha, delta, dr);
                res.w = pcen_h(xv.w, M, alpha, delta, dr);
                sm4[b4 + k] = res;
            }
        } else {
            #pragma unroll
            for (int k = 0; k < 4; ++k) {
                const float4 xv = sm4[b4 + k];
                float4 res;
                res.x = pcen_g(xv.x, M, alpha, r, delta, dr);
                res.y = pcen_g(xv.y, M, alpha, r, delta, dr);
                res.z = pcen_g(xv.z, M, alpha, r, delta, dr);
                res.w = pcen_g(xv.w, M, alpha, r, delta, dr);
                sm4[b4 + k] = res;
            }
        }
    }

    __syncthreads();

    // ---- Phase 4: coalesced STG.128 ----
    if (interior) {
        #pragma unroll
        for (int k = 0; k < 4; ++k) {
            const int j4 = tid + k * BLOCK;
            out4[rowBase4 + tile0_4 + j4] = sm4[SM4(j4 + HALO / 4)];
        }
    } else {
        #pragma unroll
        for (int k = 0; k < 4; ++k) {
            const int j4 = tid + k * BLOCK;
            const int t4 = tile0_4 + j4;
            if (t4 < T4) out4[rowBase4 + t4] = sm4[SM4(j4 + HALO / 4)];
        }
    }
}

extern "C" void kernel_launch(void* const* d_in, const int* in_sizes, int n_in,
                              void* d_out, int out_size)
{
    const float4* data4   = (const float4*)d_in[0];
    const float*  alpha_p = (const float*)d_in[1];
    const float*  r_p     = (const float*)d_in[2];
    const float*  delta_p = (const float*)d_in[3];
    float4* out4 = (float4*)d_out;

    const int total = in_sizes[0];
    const int T  = total / F_DIM;                   // 50000
    const int T4 = T / 4;                           // 12500
    const int tilesPerRow = (T + TILE - 1) / TILE;  // 13

    dim3 grid(tilesPerRow, F_DIM);
    pcen_kernel<<<grid, BLOCK>>>(data4, alpha_p, r_p, delta_p, out4, T4);
}